// round 6
// baseline (speedup 1.0000x reference)
#include <cuda_runtime.h>
#include <math.h>

#define V_NODES 2048
#define D_F     128
#define NJ      8
#define NCHUNK  128
#define VC      (V_NODES / NCHUNK)   // 16 nodes per chunk
#define NP      73                   // 1 + J + J^2

__device__ float g_lam[NJ * V_NODES];            // lam[j][v]
__device__ float g_partial[NCHUNK * NP * D_F];   // partial[c][p][d]

// ---------------------------------------------------------------------------
// Kernel 1: deg[v] = sum_b W[v,b]; then the 8 filter responses at E=deg[v].
// One block per row, 256 threads, float4 loads (16 MB total = the HBM floor).
// ---------------------------------------------------------------------------
__global__ void __launch_bounds__(256) k_deg_lam(const float* __restrict__ W) {
    const int row = blockIdx.x;
    const int tid = threadIdx.x;
    const float4* Wr = reinterpret_cast<const float4*>(W + (size_t)row * V_NODES);
    float4 x0 = Wr[tid];
    float4 x1 = Wr[tid + 256];
    float s = ((x0.x + x0.y) + (x0.z + x0.w)) + ((x1.x + x1.y) + (x1.z + x1.w));
    #pragma unroll
    for (int off = 16; off; off >>= 1) s += __shfl_down_sync(0xffffffffu, s, off);
    __shared__ float sw[8];
    if ((tid & 31) == 0) sw[tid >> 5] = s;
    __syncthreads();
    if (tid == 0) {
        float deg = 0.f;
        #pragma unroll
        for (int i = 0; i < 8; i++) deg += sw[i];
        // Lmat diagonal entry = deg * dhalf^2, dhalf^2 = 1/max(1,deg); E = |.|
        float dh2  = 1.0f / fmaxf(1.0f, deg);
        float E    = fabsf(deg * dh2);
        float logE = logf(E);
        const float A   = 3.0f * 0.69314718055994531f / 6.0f;  // R*ln(2)/(J-R+1)
        const float PI2 = 6.28318530717958648f;
        float ssum = 1.125f;   // (R/2)*sum(d^2) + (R/2)*d0^2 = 0.75 + 0.375
        #pragma unroll
        for (int j = 2; j <= NJ; j++) {
            float x   = logE - A * (float)(j - 1) / 3.0f;
            float wav = 0.0f;
            if (x > -A && x <= 0.0f)
                wav = 0.5f - 0.5f * cosf(PI2 * x / A);   // d=(0.5,0.5),K=1 closed form
            ssum -= wav * wav;
            g_lam[(j - 1) * V_NODES + row] = wav;
        }
        g_lam[row] = sqrtf(fmaxf(ssum, 0.0f));            // scaling function
    }
}

// ---------------------------------------------------------------------------
// Kernel 2: per v-chunk partial sums.
//   a0[d]        = sum_v f[v,d]
//   a1[j][d]     = sum_v lam_j[v] * |f[v,d]|
//   a2[j1,j2][d] = sum_v lam_j1[v]*lam_j2[v]*|f[v,d]|   (symmetric: 36 accums)
// 128 threads = one d each; chunk of VC=16 nodes.
// ---------------------------------------------------------------------------
__global__ void __launch_bounds__(128) k_accum(const float* __restrict__ f) {
    const int tid = threadIdx.x;       // d index
    const int c   = blockIdx.x;
    const int v0  = c * VC;

    __shared__ float sl[NJ][VC];
    {
        int j = tid >> 4, vv = tid & 15;   // 8*16 = 128 loads, one per thread
        sl[j][vv] = g_lam[j * V_NODES + v0 + vv];
    }
    __syncthreads();

    float a0 = 0.f, a1[NJ], a2[36];
    #pragma unroll
    for (int i = 0; i < NJ; i++) a1[i] = 0.f;
    #pragma unroll
    for (int i = 0; i < 36; i++) a2[i] = 0.f;

    #pragma unroll
    for (int v = 0; v < VC; v++) {
        float fv = f[(size_t)(v0 + v) * D_F + tid];
        float af = fabsf(fv);
        a0 += fv;
        float w[NJ], p[NJ];
        #pragma unroll
        for (int j = 0; j < NJ; j++) {
            w[j] = sl[j][v];
            p[j] = w[j] * af;
            a1[j] += p[j];
        }
        int idx = 0;
        #pragma unroll
        for (int j1 = 0; j1 < NJ; j1++) {
            #pragma unroll
            for (int j2 = j1; j2 < NJ; j2++) {
                a2[idx] += w[j2] * p[j1];
                idx++;
            }
        }
    }

    float* pp = g_partial + (size_t)c * (NP * D_F);
    pp[tid] = a0;
    #pragma unroll
    for (int j = 0; j < NJ; j++) pp[(1 + j) * D_F + tid] = a1[j];
    #pragma unroll
    for (int j1 = 0; j1 < NJ; j1++) {
        #pragma unroll
        for (int j2 = 0; j2 < NJ; j2++) {
            int lo = j1 < j2 ? j1 : j2;
            int hi = j1 < j2 ? j2 : j1;
            int sidx = lo * 8 - (lo * (lo - 1)) / 2 + (hi - lo);
            pp[(1 + NJ + j1 * NJ + j2) * D_F + tid] = a2[sidx];
        }
    }
}

// ---------------------------------------------------------------------------
// Kernel 3: deterministic fixed-order reduction over the 128 chunks + /V.
// 73 blocks x 512 threads: 4 c-lanes of 32 chunks each per output element.
// ---------------------------------------------------------------------------
__global__ void __launch_bounds__(512) k_reduce(float* __restrict__ out) {
    const int t = threadIdx.x & 127;
    const int q = threadIdx.x >> 7;          // 0..3
    const int o = blockIdx.x * D_F + t;      // output element (p*128 + d)
    const int c0 = q * (NCHUNK / 4);
    float s = 0.f;
    #pragma unroll
    for (int i = 0; i < NCHUNK / 4; i++)
        s += g_partial[(size_t)(c0 + i) * (NP * D_F) + o];
    __shared__ float sh[4][D_F];
    sh[q][t] = s;
    __syncthreads();
    if (q == 0) {
        float r = ((sh[0][t] + sh[1][t]) + sh[2][t]) + sh[3][t];
        out[o] = r * (1.0f / (float)V_NODES);
    }
}

// ---------------------------------------------------------------------------
extern "C" void kernel_launch(void* const* d_in, const int* in_sizes, int n_in,
                              void* d_out, int out_size) {
    // metadata order: W [V,V], f [V,d_f]; identify defensively by size.
    const float* W = (const float*)d_in[0];
    const float* f = (const float*)d_in[1];
    if (n_in >= 2 && in_sizes[0] != V_NODES * V_NODES) {
        W = (const float*)d_in[1];
        f = (const float*)d_in[0];
    }
    float* out = (float*)d_out;

    k_deg_lam<<<V_NODES, 256>>>(W);
    k_accum  <<<NCHUNK, 128>>>(f);
    k_reduce <<<NP, 512>>>(out);
}

// round 8
// speedup vs baseline: 1.2149x; 1.2149x over previous
#include <cuda_runtime.h>
#include <math.h>

#define V_NODES 2048
#define D_F     128
#define NJ      8
#define NCHUNK  128
#define VC      (V_NODES / NCHUNK)   // 16 nodes per chunk
#define NP      73                   // 1 + J + J^2 (output planes)
#define NPU     45                   // 1 + J + J*(J+1)/2 (unique planes stored)
#define ROWS_PB 16                   // rows per block in k1

__device__ float g_lam[NJ * V_NODES];             // lam[j][v]
__device__ float g_partial[NCHUNK * NPU * D_F];   // partial[c][pu][d]

// ---------------------------------------------------------------------------
// Kernel 1: deg[v] = row sums of W, then the 8 filter responses at E.
// 128 blocks x 1024 threads; 16 rows/block, 2 warps/row, 8 float4/thread
// (MLP=8 front-batched) -> DRAM-bound streaming of the 16 MB of W.
// ---------------------------------------------------------------------------
__global__ void __launch_bounds__(1024) k_deg_lam(const float* __restrict__ W) {
    const int warp = threadIdx.x >> 5;
    const int lane = threadIdx.x & 31;
    const int rib  = warp >> 1;                   // row within block (0..15)
    const int par  = warp & 1;                    // which half of the row
    const int row  = blockIdx.x * ROWS_PB + rib;

    const float4* Wr = reinterpret_cast<const float4*>(W + (size_t)row * V_NODES);
    float4 x[8];
    #pragma unroll
    for (int i = 0; i < 8; i++)                   // front-batched: 8 LDG.128 in flight
        x[i] = Wr[lane + 32 * par + 64 * i];
    float s = 0.f;
    #pragma unroll
    for (int i = 0; i < 8; i++)
        s += ((x[i].x + x[i].y) + (x[i].z + x[i].w));
    #pragma unroll
    for (int off = 16; off; off >>= 1) s += __shfl_down_sync(0xffffffffu, s, off);

    __shared__ float sw[32];
    if (lane == 0) sw[warp] = s;
    __syncthreads();

    if (threadIdx.x < ROWS_PB) {
        const int r   = blockIdx.x * ROWS_PB + threadIdx.x;
        float deg = sw[2 * threadIdx.x] + sw[2 * threadIdx.x + 1];
        // Lmat diagonal entry = deg * dhalf^2, dhalf^2 = 1/max(1,deg); E = |.|
        float dh2  = 1.0f / fmaxf(1.0f, deg);
        float E    = fabsf(deg * dh2);
        float logE = logf(E);
        const float A   = 3.0f * 0.69314718055994531f / 6.0f;  // R*ln(2)/(J-R+1)
        const float PI2 = 6.28318530717958648f;
        float ssum = 1.125f;   // (R/2)*sum(d^2) + (R/2)*d0^2
        #pragma unroll
        for (int j = 2; j <= NJ; j++) {
            float xx  = logE - A * (float)(j - 1) / 3.0f;
            float wav = 0.0f;
            if (xx > -A && xx <= 0.0f)
                wav = 0.5f - 0.5f * cosf(PI2 * xx / A);  // d=(0.5,0.5),K=1 closed form
            ssum -= wav * wav;
            g_lam[(j - 1) * V_NODES + r] = wav;
        }
        g_lam[r] = sqrtf(fmaxf(ssum, 0.0f));             // scaling function
    }
}

// ---------------------------------------------------------------------------
// Kernel 2: per v-chunk partial sums; stores ONLY the 45 unique planes:
//   plane 0        : sum_v f[v,d]
//   planes 1..8    : sum_v lam_j[v] * |f[v,d]|
//   planes 9..44   : sum_v lam_j1*lam_j2*|f[v,d]| for j1<=j2 (upper triangle)
// ---------------------------------------------------------------------------
__global__ void __launch_bounds__(128) k_accum(const float* __restrict__ f) {
    const int tid = threadIdx.x;       // d index
    const int c   = blockIdx.x;
    const int v0  = c * VC;

    __shared__ float sl[NJ][VC];
    {
        int j = tid >> 4, vv = tid & 15;   // 8*16 = 128 loads, one per thread
        sl[j][vv] = g_lam[j * V_NODES + v0 + vv];
    }
    __syncthreads();

    float a0 = 0.f, a1[NJ], a2[36];
    #pragma unroll
    for (int i = 0; i < NJ; i++) a1[i] = 0.f;
    #pragma unroll
    for (int i = 0; i < 36; i++) a2[i] = 0.f;

    #pragma unroll
    for (int v = 0; v < VC; v++) {
        float fv = f[(size_t)(v0 + v) * D_F + tid];
        float af = fabsf(fv);
        a0 += fv;
        float w[NJ], p[NJ];
        #pragma unroll
        for (int j = 0; j < NJ; j++) {
            w[j] = sl[j][v];
            p[j] = w[j] * af;
            a1[j] += p[j];
        }
        int idx = 0;
        #pragma unroll
        for (int j1 = 0; j1 < NJ; j1++) {
            #pragma unroll
            for (int j2 = j1; j2 < NJ; j2++) {
                a2[idx] += w[j2] * p[j1];
                idx++;
            }
        }
    }

    float* pp = g_partial + (size_t)c * (NPU * D_F);
    pp[tid] = a0;
    #pragma unroll
    for (int j = 0; j < NJ; j++) pp[(1 + j) * D_F + tid] = a1[j];
    #pragma unroll
    for (int i = 0; i < 36; i++) pp[(1 + NJ + i) * D_F + tid] = a2[i];
}

// ---------------------------------------------------------------------------
// Kernel 3: deterministic fixed-order reduction over the 128 chunks + /V.
// 73 blocks x 512 threads; each output plane maps to its unique stored plane
// (symmetric (j1,j2) pairs read the same plane -> L2 hits).
// ---------------------------------------------------------------------------
__global__ void __launch_bounds__(512) k_reduce(float* __restrict__ out) {
    const int t = threadIdx.x & 127;
    const int q = threadIdx.x >> 7;          // 0..3 (four 32-chunk lanes)
    const int p = blockIdx.x;                // output plane 0..72

    int plane;
    if (p < 1 + NJ) {
        plane = p;
    } else {
        int qq = p - (1 + NJ);
        int j1 = qq >> 3, j2 = qq & 7;
        int lo = j1 < j2 ? j1 : j2;
        int hi = j1 < j2 ? j2 : j1;
        plane = 1 + NJ + lo * NJ - (lo * (lo - 1)) / 2 + (hi - lo);
    }

    const int c0 = q * (NCHUNK / 4);
    float s = 0.f;
    #pragma unroll
    for (int i = 0; i < NCHUNK / 4; i++)
        s += g_partial[(size_t)(c0 + i) * (NPU * D_F) + plane * D_F + t];

    __shared__ float sh[4][D_F];
    sh[q][t] = s;
    __syncthreads();
    if (q == 0) {
        float r = ((sh[0][t] + sh[1][t]) + sh[2][t]) + sh[3][t];
        out[p * D_F + t] = r * (1.0f / (float)V_NODES);
    }
}

// ---------------------------------------------------------------------------
extern "C" void kernel_launch(void* const* d_in, const int* in_sizes, int n_in,
                              void* d_out, int out_size) {
    // metadata order: W [V,V], f [V,d_f]; identify defensively by size.
    const float* W = (const float*)d_in[0];
    const float* f = (const float*)d_in[1];
    if (n_in >= 2 && in_sizes[0] != V_NODES * V_NODES) {
        W = (const float*)d_in[1];
        f = (const float*)d_in[0];
    }
    float* out = (float*)d_out;

    k_deg_lam<<<V_NODES / ROWS_PB, 1024>>>(W);
    k_accum  <<<NCHUNK, 128>>>(f);
    k_reduce <<<NP, 512>>>(out);
}